// round 13
// baseline (speedup 1.0000x reference)
#include <cuda_runtime.h>
#include <cuda_pipeline.h>
#include <math.h>

#define B 64
#define P 8732
#define M 16
#define C 81
#define EPSF 1e-7f
#define L2E 1.4426950408889634f
#define LN2 0.6931471805599453f

// ---------------- device scratch ----------------
__device__ __align__(16) float g_conf_neg[B * P];
__device__ unsigned char       g_tc[B * P];
__device__ unsigned long long  g_best[B * M];    // packed (iou_bits<<32)|~prior_idx
__device__ unsigned int        g_force[B * M];   // (prior<<8)|(j+1), 0 = none
__device__ int                 g_n_pos[B];
__device__ double              g_conf_pos[B];
__device__ double              g_loc_pb[B];
__device__ double              g_hard_pb[B];
__device__ unsigned int        g_done;
__device__ unsigned int        g_obj_done;

// ---------------- helpers ----------------
__device__ __forceinline__ float ex2f(float x) {
    float y; asm("ex2.approx.ftz.f32 %0, %1;" : "=f"(y) : "f"(x)); return y;
}
__device__ __forceinline__ float lg2f(float x) {
    float y; asm("lg2.approx.ftz.f32 %0, %1;" : "=f"(y) : "f"(x)); return y;
}

__device__ __forceinline__ double blockReduceSumD(double v) {
    __shared__ double sh[32];
    int lane = threadIdx.x & 31, wid = threadIdx.x >> 5;
    #pragma unroll
    for (int o = 16; o; o >>= 1) v += __shfl_down_sync(0xffffffffu, v, o);
    if (lane == 0) sh[wid] = v;
    __syncthreads();
    int nw = (blockDim.x + 31) >> 5;
    v = (threadIdx.x < (unsigned)nw) ? sh[threadIdx.x] : 0.0;
    if (wid == 0) {
        #pragma unroll
        for (int o = 16; o; o >>= 1) v += __shfl_down_sync(0xffffffffu, v, o);
    }
    __syncthreads();
    return v;  // valid in thread 0
}

// ---------------- K1: per-object best prior (block per (b,m)); last block builds override table ----------------
#define OBJ_TPB    256
#define OBJ_GRID   (B * M)           // 1024 blocks
__global__ void __launch_bounds__(OBJ_TPB)
k_obj(const float4* __restrict__ boxes,
      const float4* __restrict__ priors) {
    const int bm   = blockIdx.x;
    const int tid  = threadIdx.x;
    const int lane = tid & 31;
    const int wid  = tid >> 5;

    if (bm == 0) {
        if (tid < B) { g_conf_pos[tid] = 0.0; g_loc_pb[tid] = 0.0; g_n_pos[tid] = 0; }
        if (tid == B) g_done = 0u;
    }

    __shared__ unsigned long long wred[OBJ_TPB / 32];
    __shared__ int s_last;

    float4 bx = __ldg(&boxes[bm]);
    float areab = (bx.z - bx.x) * (bx.w - bx.y);

    unsigned long long vmax = 0ull;
    for (int p = tid; p < P; p += OBJ_TPB) {
        float4 pc = __ldg(&priors[p]);
        float px0 = pc.x - pc.z * 0.5f;
        float py0 = pc.y - pc.w * 0.5f;
        float px1 = pc.x + pc.z * 0.5f;
        float py1 = pc.y + pc.w * 0.5f;
        float areap = (px1 - px0) * (py1 - py0);
        float iw = fmaxf(fminf(bx.z, px1) - fmaxf(bx.x, px0), 0.0f);
        float ih = fmaxf(fminf(bx.w, py1) - fmaxf(bx.y, py0), 0.0f);
        float inter = iw * ih;
        float iou = __fdividef(inter, areab + areap - inter);
        unsigned long long pk =
            ((unsigned long long)__float_as_uint(iou) << 32) |
            (unsigned long long)(~(unsigned int)p);      // ties -> smallest p
        if (pk > vmax) vmax = pk;
    }
    #pragma unroll
    for (int o = 16; o; o >>= 1) {
        unsigned long long u = __shfl_down_sync(0xffffffffu, vmax, o);
        if (u > vmax) vmax = u;
    }
    if (lane == 0) wred[wid] = vmax;
    __syncthreads();
    if (tid == 0) {
        unsigned long long v = wred[0];
        #pragma unroll
        for (int w = 1; w < OBJ_TPB / 32; w++)
            if (wred[w] > v) v = wred[w];
        g_best[bm] = v;
    }

    // ---- last block builds g_force (in-order scatter semantics + faithful j_idx) ----
    __threadfence();
    if (tid == 0) {
        unsigned int t = atomicAdd(&g_obj_done, 1u);
        s_last = (t == OBJ_GRID - 1u) ? 1 : 0;
    }
    __syncthreads();
    if (s_last) {
        if (tid < B) {
            const int bb = tid;
            int j = -1;
            #pragma unroll
            for (int mm = 0; mm < M; mm++) {
                unsigned long long v = g_best[bb * M + mm];
                unsigned int e = 0u;
                if (v >> 32) {
                    j++;
                    unsigned int pp = ~(unsigned int)(v & 0xffffffffull);
                    e = (pp << 8) | (unsigned int)(j + 1);
                }
                g_force[bb * M + mm] = e;
            }
        }
        if (tid == 0) g_obj_done = 0u;
    }
}

// ---------------- K2: per-prior matcher -> true class (1 byte per row) ----------------
#define MT        256
#define MCHUNK    ((P + MT - 1) / MT)    // 35
#define MGRID     (B * MCHUNK)           // 2240
__global__ void __launch_bounds__(MT)
k_match(const float4* __restrict__ boxes,
        const int*    __restrict__ labels,
        const float4* __restrict__ priors) {
    const int b     = blockIdx.x / MCHUNK;
    const int chunk = blockIdx.x % MCHUNK;
    const int tid   = threadIdx.x;
    const int p0    = chunk * MT;
    const int p     = p0 + tid;
    const bool valid = p < P;

    __shared__ float4        sbox[M];
    __shared__ float         sarea[M];
    __shared__ unsigned char slab[M];
    __shared__ unsigned char sforce[MT];
    if (tid < M) {
        float4 bx = boxes[b * M + tid];
        sbox[tid]  = bx;
        sarea[tid] = (bx.z - bx.x) * (bx.w - bx.y);
        slab[tid]  = (unsigned char)labels[b * M + tid];
    }
    sforce[tid] = 0;
    __syncthreads();
    if (tid == 0) {
        #pragma unroll
        for (int mm = 0; mm < M; mm++) {
            unsigned int e = g_force[b * M + mm];
            if (e) {
                int pp = (int)(e >> 8);
                if (pp >= p0 && pp < p0 + MT) sforce[pp - p0] = (unsigned char)(e & 0xffu);
            }
        }
    }
    __syncthreads();

    float px0 = 0.f, py0 = 0.f, px1 = 0.f, py1 = 0.f, areap = 0.f;
    if (valid) {
        float4 pc = priors[p];
        px0 = pc.x - pc.z * 0.5f;
        py0 = pc.y - pc.w * 0.5f;
        px1 = pc.x + pc.z * 0.5f;
        py1 = pc.y + pc.w * 0.5f;
        areap = (px1 - px0) * (py1 - py0);
    }

    float bv = -1.0f; int bm = 0;
    #pragma unroll
    for (int m = 0; m < M; m++) {
        float4 bx = sbox[m];
        float iw = fmaxf(fminf(bx.z, px1) - fmaxf(bx.x, px0), 0.0f);
        float ih = fmaxf(fminf(bx.w, py1) - fmaxf(bx.y, py0), 0.0f);
        float inter = iw * ih;
        float iou = __fdividef(inter, sarea[m] + areap - inter);
        if (iou > bv) { bv = iou; bm = m; }   // first-max over m (same math as reference)
    }
    unsigned char f = sforce[tid];
    if (f) { bv = 1.0f; bm = f - 1; }         // override: ovl=1, obj=j (filtered index)
    if (valid)
        g_tc[b * P + p] = (bv < 0.5f) ? (unsigned char)0 : slab[bm];
}

// ---------------- K3: CE loss, warp-private 8-row tiles, double-buffered, lean registers ----------------
#define CW        8                   // warps per block
#define WROWS     8                   // rows per warp-tile
#define WTILE_F   (WROWS * C)         // 648 floats
#define WTILE_V4  (WTILE_F / 4)       // 162
#define WNT       (B * P / WROWS)     // 69856 exact
#define WGRID     740                 // 5 blocks/SM (41.5 KB/block)
#define WSMEM     (CW * 2 * WTILE_F * 4)   // 41472 B dynamic

__global__ void __launch_bounds__(CW * 32)
k_conf(const float4* __restrict__ scores4,
       const float4* __restrict__ locs) {
    extern __shared__ float sm[];
    const int wid  = threadIdx.x >> 5;
    const int lane = threadIdx.x & 31;
    const int sub  = lane & 3;
    const int r    = lane >> 2;       // 0..7 row within warp-tile
    float* bufs[2] = { sm + wid * 2 * WTILE_F,
                       sm + wid * 2 * WTILE_F + WTILE_F };

    const int gw = blockIdx.x * CW + wid;
    const int nw = WGRID * CW;

    int t = gw;
    if (t < WNT) {
        const float4* src = scores4 + (size_t)t * WTILE_V4;
        float4* dst = (float4*)bufs[0];
        #pragma unroll
        for (int i = 0; i < 6; i++) {
            int idx = lane + i * 32;
            if (idx < WTILE_V4) __pipeline_memcpy_async(&dst[idx], &src[idx], 16);
        }
    }
    __pipeline_commit();

    int cur = 0;
    for (; t < WNT; t += nw) {
        int tn = t + nw;
        if (tn < WNT) {
            const float4* src = scores4 + (size_t)tn * WTILE_V4;
            float4* dst = (float4*)bufs[cur ^ 1];
            #pragma unroll
            for (int i = 0; i < 6; i++) {
                int idx = lane + i * 32;
                if (idx < WTILE_V4) __pipeline_memcpy_async(&dst[idx], &src[idx], 16);
            }
        }
        __pipeline_commit();

        // independent long-latency load: this row's true class (sub 0 only uses it)
        const int row = t * WROWS + r;
        int tc = (int)g_tc[row];

        __pipeline_wait_prior(1);
        __syncwarp();

        const float* rp = bufs[cur] + r * C;
        float s0, s1, s2, s3;
        s0 = ex2f(rp[sub]      * L2E);
        s1 = ex2f(rp[sub + 4]  * L2E);
        s2 = ex2f(rp[sub + 8]  * L2E);
        s3 = ex2f(rp[sub + 12] * L2E);
        s0 += ex2f(rp[sub + 16] * L2E);
        s1 += ex2f(rp[sub + 20] * L2E);
        s2 += ex2f(rp[sub + 24] * L2E);
        s3 += ex2f(rp[sub + 28] * L2E);
        s0 += ex2f(rp[sub + 32] * L2E);
        s1 += ex2f(rp[sub + 36] * L2E);
        s2 += ex2f(rp[sub + 40] * L2E);
        s3 += ex2f(rp[sub + 44] * L2E);
        s0 += ex2f(rp[sub + 48] * L2E);
        s1 += ex2f(rp[sub + 52] * L2E);
        s2 += ex2f(rp[sub + 56] * L2E);
        s3 += ex2f(rp[sub + 60] * L2E);
        s0 += ex2f(rp[sub + 64] * L2E);
        s1 += ex2f(rp[sub + 68] * L2E);
        s2 += ex2f(rp[sub + 72] * L2E);
        s3 += ex2f(rp[sub + 76] * L2E);
        float s = (s0 + s1) + (s2 + s3);
        if (sub == 0) s += ex2f(rp[80] * L2E);
        s += __shfl_xor_sync(0xffffffffu, s, 1);
        s += __shfl_xor_sync(0xffffffffu, s, 2);

        if (sub == 0) {
            const int b = row / P;
            float conf = lg2f(s) * LN2 - rp[tc];   // -(log_softmax[tc]) >= 0
            bool pos = tc > 0;
            g_conf_neg[row] = pos ? 0.0f : conf;
            if (pos) {
                atomicAdd(&g_conf_pos[b], (double)conf);
                atomicAdd(&g_n_pos[b], 1);
                float4 bx = locs[row];
                float iw = fmaxf(bx.z - bx.x, 0.0f);
                float ih = fmaxf(bx.w - bx.y, 0.0f);
                float inter = iw * ih;
                float area = (bx.z - bx.x) * (bx.w - bx.y);
                float iou = __fdividef(inter, area + area - inter + EPSF);
                float dious = fminf(fmaxf(iou, -1.0f), 1.0f);  // inter_diag==0 exactly
                atomicAdd(&g_loc_pb[b], (double)(1.0f - dious));
            }
        }
        __syncwarp();
        cur ^= 1;
    }
}

// ---------------- K4: per-batch top-k sum, 3-pass (11/11/10-bit) radix select ----------------
#define TKT 1024
__global__ void __launch_bounds__(TKT)
k_topk(float* __restrict__ out) {
    const int b    = blockIdx.x;
    const int tid  = threadIdx.x;
    const int lane = tid & 31;
    const int wid  = tid >> 5;

    __shared__ unsigned int sv[P];     // 34928 B
    __shared__ int hist[2048];         // 8192 B
    __shared__ int wtot[32], wsuf[33];
    __shared__ int s_bin, s_kk;
    __shared__ int s_last;

    {
        const uint4* src = (const uint4*)(g_conf_neg + b * P);
        uint4* dst = (uint4*)sv;
        for (int i = tid; i < P / 4; i += TKT) dst[i] = src[i];
    }
    __syncthreads();

    long long k = 3LL * (long long)g_n_pos[b];
    double result = 0.0;

    if (k >= P) {
        double sum = 0.0;
        for (int p = tid; p < P; p += TKT) sum += (double)__uint_as_float(sv[p]);
        result = blockReduceSumD(sum);
    } else if (k > 0) {
        unsigned int prefix = 0;
        int kk = (int)k;
        #pragma unroll
        for (int pass = 0; pass < 3; pass++) {
            const int sh   = (pass == 0) ? 21 : (pass == 1) ? 10 : 0;
            const int bits = (pass == 2) ? 10 : 11;
            const unsigned int dmask = (1u << bits) - 1u;
            hist[tid] = 0; hist[tid + 1024] = 0;
            __syncthreads();
            for (int base = 0; base < P; base += TKT) {
                int p = base + tid;
                bool in = p < P;
                unsigned int v = in ? sv[p] : 0u;
                bool match = in && (pass == 0 || (v >> (sh + bits)) == prefix);
                unsigned int act = __ballot_sync(0xffffffffu, match);
                if (match) {
                    unsigned int bin = (v >> sh) & dmask;
                    unsigned int peers = __match_any_sync(act, bin);
                    if ((__ffs(peers) - 1) == lane)
                        atomicAdd(&hist[bin], (int)__popc(peers));
                }
            }
            __syncthreads();
            // block-wide suffix scan: thread owns bins 2*tid, 2*tid+1
            int h_lo = hist[2 * tid], h_hi = hist[2 * tid + 1];
            int tot = h_lo + h_hi;
            int v = tot;
            #pragma unroll
            for (int o = 1; o < 32; o <<= 1) {
                int u = __shfl_down_sync(0xffffffffu, v, o);
                if (lane + o < 32) v += u;
            }
            if (lane == 0) wtot[wid] = v;
            __syncthreads();
            if (wid == 0) {
                int x = wtot[lane];
                #pragma unroll
                for (int o = 1; o < 32; o <<= 1) {
                    int u = __shfl_down_sync(0xffffffffu, x, o);
                    if (lane + o < 32) x += u;
                }
                wsuf[lane] = x;
                if (lane == 0) wsuf[32] = 0;
            }
            __syncthreads();
            int after = (v - tot) + wsuf[wid + 1];   // strictly after this thread
            int cge0 = tot + after;
            int cge1 = h_hi + after;
            int cge2 = after;
            if (cge0 >= kk && cge1 < kk) { s_bin = 2 * tid;     s_kk = kk - cge1; }
            if (cge1 >= kk && cge2 < kk) { s_bin = 2 * tid + 1; s_kk = kk - cge2; }
            __syncthreads();
            prefix = (prefix << bits) | (unsigned int)s_bin;
            kk = s_kk;
            __syncthreads();
        }
        unsigned int thr = prefix;   // exact k-th largest bit pattern
        double sum = 0.0;
        for (int p = tid; p < P; p += TKT) {
            unsigned int v = sv[p];
            if (v > thr) sum += (double)__uint_as_float(v);
        }
        result = blockReduceSumD(sum);
        if (tid == 0) result += (double)kk * (double)__uint_as_float(thr);
    }
    if (tid == 0) g_hard_pb[b] = result;

    // ---- fused final: last block combines everything ----
    __threadfence();
    if (tid == 0) {
        unsigned int t = atomicAdd(&g_done, 1u);
        s_last = (t == B - 1u) ? 1 : 0;
    }
    __syncthreads();
    if (s_last) {
        double cp = 0.0, hs = 0.0, ls = 0.0;
        long long np = 0;
        if (tid < B) {
            cp = g_conf_pos[tid];
            hs = g_hard_pb[tid];
            ls = g_loc_pb[tid];
            np = g_n_pos[tid];
        }
        double cps = blockReduceSumD(cp);
        double hss = blockReduceSumD(hs);
        double lss = blockReduceSumD(ls);
        double nps = blockReduceSumD((double)np);
        if (tid == 0) {
            float conf_loss = (float)((hss + cps) / nps);
            float loc_loss  = (float)(lss / fmax(nps, 1.0));
            out[0] = conf_loss + loc_loss;  // ALPHA = 1.0
        }
    }
}

// ---------------- launch ----------------
extern "C" void kernel_launch(void* const* d_in, const int* in_sizes, int n_in,
                              void* d_out, int out_size) {
    const float* locs   = (const float*)d_in[0];  // [B,P,4]
    const float* scores = (const float*)d_in[1];  // [B,P,C]
    const float* boxes  = (const float*)d_in[2];  // [B,M,4]
    const int*   labels = (const int*)  d_in[3];  // [B,M]
    const float* priors = (const float*)d_in[4];  // [P,4]
    float* out = (float*)d_out;

    cudaFuncSetAttribute(k_conf, cudaFuncAttributeMaxDynamicSharedMemorySize, WSMEM);

    k_obj<<<OBJ_GRID, OBJ_TPB>>>((const float4*)boxes, (const float4*)priors);
    k_match<<<MGRID, MT>>>((const float4*)boxes, labels, (const float4*)priors);
    k_conf<<<WGRID, CW * 32, WSMEM>>>((const float4*)scores, (const float4*)locs);
    k_topk<<<B, TKT>>>(out);
}

// round 14
// speedup vs baseline: 1.0285x; 1.0285x over previous
#include <cuda_runtime.h>
#include <math.h>

#define B 64
#define P 8732
#define M 16
#define C 81
#define EPSF 1e-7f
#define L2E 1.4426950408889634f
#define LN2 0.6931471805599453f

// ---------------- device scratch ----------------
__device__ __align__(16) float g_conf_neg[B * P];
__device__ unsigned char       g_tc[B * P];
__device__ unsigned long long  g_best[B * M];    // packed (iou_bits<<32)|~prior_idx
__device__ unsigned int        g_force[B * M];   // (prior<<8)|(j+1), 0 = none
__device__ int                 g_n_pos[B];
__device__ double              g_conf_pos[B];
__device__ double              g_loc_pb[B];
__device__ double              g_hard_pb[B];
__device__ unsigned int        g_done;
__device__ unsigned int        g_obj_done;

// ---------------- helpers ----------------
__device__ __forceinline__ float ex2f(float x) {
    float y; asm("ex2.approx.ftz.f32 %0, %1;" : "=f"(y) : "f"(x)); return y;
}
__device__ __forceinline__ float lg2f(float x) {
    float y; asm("lg2.approx.ftz.f32 %0, %1;" : "=f"(y) : "f"(x)); return y;
}

__device__ __forceinline__ double blockReduceSumD(double v) {
    __shared__ double sh[32];
    int lane = threadIdx.x & 31, wid = threadIdx.x >> 5;
    #pragma unroll
    for (int o = 16; o; o >>= 1) v += __shfl_down_sync(0xffffffffu, v, o);
    if (lane == 0) sh[wid] = v;
    __syncthreads();
    int nw = (blockDim.x + 31) >> 5;
    v = (threadIdx.x < (unsigned)nw) ? sh[threadIdx.x] : 0.0;
    if (wid == 0) {
        #pragma unroll
        for (int o = 16; o; o >>= 1) v += __shfl_down_sync(0xffffffffu, v, o);
    }
    __syncthreads();
    return v;  // valid in thread 0
}

// ---------------- K1: per-object best prior (block per (b,m)); last block builds override table ----------------
#define OBJ_TPB    256
#define OBJ_GRID   (B * M)           // 1024 blocks
__global__ void __launch_bounds__(OBJ_TPB)
k_obj(const float4* __restrict__ boxes,
      const float4* __restrict__ priors) {
    const int bm   = blockIdx.x;
    const int tid  = threadIdx.x;
    const int lane = tid & 31;
    const int wid  = tid >> 5;

    if (bm == 0) {
        if (tid < B) { g_conf_pos[tid] = 0.0; g_loc_pb[tid] = 0.0; g_n_pos[tid] = 0; }
        if (tid == B) g_done = 0u;
    }

    __shared__ unsigned long long wred[OBJ_TPB / 32];
    __shared__ int s_last;

    float4 bx = __ldg(&boxes[bm]);
    float areab = (bx.z - bx.x) * (bx.w - bx.y);

    unsigned long long vmax = 0ull;
    for (int p = tid; p < P; p += OBJ_TPB) {
        float4 pc = __ldg(&priors[p]);
        float px0 = pc.x - pc.z * 0.5f;
        float py0 = pc.y - pc.w * 0.5f;
        float px1 = pc.x + pc.z * 0.5f;
        float py1 = pc.y + pc.w * 0.5f;
        float areap = (px1 - px0) * (py1 - py0);
        float iw = fmaxf(fminf(bx.z, px1) - fmaxf(bx.x, px0), 0.0f);
        float ih = fmaxf(fminf(bx.w, py1) - fmaxf(bx.y, py0), 0.0f);
        float inter = iw * ih;
        float iou = __fdividef(inter, areab + areap - inter);
        unsigned long long pk =
            ((unsigned long long)__float_as_uint(iou) << 32) |
            (unsigned long long)(~(unsigned int)p);      // ties -> smallest p
        if (pk > vmax) vmax = pk;
    }
    #pragma unroll
    for (int o = 16; o; o >>= 1) {
        unsigned long long u = __shfl_down_sync(0xffffffffu, vmax, o);
        if (u > vmax) vmax = u;
    }
    if (lane == 0) wred[wid] = vmax;
    __syncthreads();
    if (tid == 0) {
        unsigned long long v = wred[0];
        #pragma unroll
        for (int w = 1; w < OBJ_TPB / 32; w++)
            if (wred[w] > v) v = wred[w];
        g_best[bm] = v;
    }

    // ---- last block builds g_force (in-order scatter semantics + faithful j_idx) ----
    __threadfence();
    if (tid == 0) {
        unsigned int t = atomicAdd(&g_obj_done, 1u);
        s_last = (t == OBJ_GRID - 1u) ? 1 : 0;
    }
    __syncthreads();
    if (s_last) {
        if (tid < B) {
            const int bb = tid;
            int j = -1;
            #pragma unroll
            for (int mm = 0; mm < M; mm++) {
                unsigned long long v = g_best[bb * M + mm];
                unsigned int e = 0u;
                if (v >> 32) {
                    j++;
                    unsigned int pp = ~(unsigned int)(v & 0xffffffffull);
                    e = (pp << 8) | (unsigned int)(j + 1);
                }
                g_force[bb * M + mm] = e;
            }
        }
        if (tid == 0) g_obj_done = 0u;
    }
}

// ---------------- K2: per-prior matcher -> true class (1 byte per row) ----------------
#define MT        256
#define MCHUNK    ((P + MT - 1) / MT)    // 35
#define MGRID     (B * MCHUNK)           // 2240
__global__ void __launch_bounds__(MT)
k_match(const float4* __restrict__ boxes,
        const int*    __restrict__ labels,
        const float4* __restrict__ priors) {
    const int b     = blockIdx.x / MCHUNK;
    const int chunk = blockIdx.x % MCHUNK;
    const int tid   = threadIdx.x;
    const int p0    = chunk * MT;
    const int p     = p0 + tid;
    const bool valid = p < P;

    __shared__ float4        sbox[M];
    __shared__ float         sarea[M];
    __shared__ unsigned char slab[M];
    __shared__ unsigned char sforce[MT];
    if (tid < M) {
        float4 bx = boxes[b * M + tid];
        sbox[tid]  = bx;
        sarea[tid] = (bx.z - bx.x) * (bx.w - bx.y);
        slab[tid]  = (unsigned char)labels[b * M + tid];
    }
    sforce[tid] = 0;
    __syncthreads();
    if (tid == 0) {
        #pragma unroll
        for (int mm = 0; mm < M; mm++) {
            unsigned int e = g_force[b * M + mm];
            if (e) {
                int pp = (int)(e >> 8);
                if (pp >= p0 && pp < p0 + MT) sforce[pp - p0] = (unsigned char)(e & 0xffu);
            }
        }
    }
    __syncthreads();

    float px0 = 0.f, py0 = 0.f, px1 = 0.f, py1 = 0.f, areap = 0.f;
    if (valid) {
        float4 pc = priors[p];
        px0 = pc.x - pc.z * 0.5f;
        py0 = pc.y - pc.w * 0.5f;
        px1 = pc.x + pc.z * 0.5f;
        py1 = pc.y + pc.w * 0.5f;
        areap = (px1 - px0) * (py1 - py0);
    }

    float bv = -1.0f; int bm = 0;
    #pragma unroll
    for (int m = 0; m < M; m++) {
        float4 bx = sbox[m];
        float iw = fmaxf(fminf(bx.z, px1) - fmaxf(bx.x, px0), 0.0f);
        float ih = fmaxf(fminf(bx.w, py1) - fmaxf(bx.y, py0), 0.0f);
        float inter = iw * ih;
        float iou = __fdividef(inter, sarea[m] + areap - inter);
        if (iou > bv) { bv = iou; bm = m; }   // first-max over m (same math as reference)
    }
    unsigned char f = sforce[tid];
    if (f) { bv = 1.0f; bm = f - 1; }         // override: ovl=1, obj=j (filtered index)
    if (valid)
        g_tc[b * P + p] = (bv < 0.5f) ? (unsigned char)0 : slab[bm];
}

// ---------------- K3: CE loss, LDG.128->regs->STS.128 staging (bypasses LDGSTS rate cap) ----------------
#define CW        8                   // warps per block
#define WROWS     8                   // rows per warp-tile
#define WTILE_F   (WROWS * C)         // 648 floats
#define WTILE_V4  (WTILE_F / 4)       // 162
#define WNT       (B * P / WROWS)     // 69856 exact
#define WGRID     592                 // 4 blocks/SM target
#define WSMEM     (CW * WTILE_F * 4)  // 20736 B dynamic (single buffer per warp)

__global__ void __launch_bounds__(CW * 32)
k_conf(const float4* __restrict__ scores4,
       const float4* __restrict__ locs) {
    extern __shared__ float sm[];
    const int wid  = threadIdx.x >> 5;
    const int lane = threadIdx.x & 31;
    const int sub  = lane & 3;
    const int r    = lane >> 2;       // 0..7 row within warp-tile
    float* buf = sm + wid * WTILE_F;

    const int gw = blockIdx.x * CW + wid;
    const int nw = WGRID * CW;

    // prologue: load tile gw into registers (warp-coalesced LDG.128)
    float4 v0, v1, v2, v3, v4, v5;
    v5 = make_float4(0.f, 0.f, 0.f, 0.f);
    int t = gw;
    if (t < WNT) {
        const float4* src = scores4 + (size_t)t * WTILE_V4;
        v0 = __ldg(&src[lane]);
        v1 = __ldg(&src[lane + 32]);
        v2 = __ldg(&src[lane + 64]);
        v3 = __ldg(&src[lane + 96]);
        v4 = __ldg(&src[lane + 128]);
        if (lane < 2) v5 = __ldg(&src[lane + 160]);
    }

    for (; t < WNT; t += nw) {
        // stage registers -> smem (STS.128, crossbar-limited, cheap)
        float4* dst = (float4*)buf;
        dst[lane]       = v0;
        dst[lane + 32]  = v1;
        dst[lane + 64]  = v2;
        dst[lane + 96]  = v3;
        dst[lane + 128] = v4;
        if (lane < 2) dst[lane + 160] = v5;
        __syncwarp();

        // issue next tile's loads (latency hides under this tile's compute)
        int tn = t + nw;
        if (tn < WNT) {
            const float4* src = scores4 + (size_t)tn * WTILE_V4;
            v0 = __ldg(&src[lane]);
            v1 = __ldg(&src[lane + 32]);
            v2 = __ldg(&src[lane + 64]);
            v3 = __ldg(&src[lane + 96]);
            v4 = __ldg(&src[lane + 128]);
            if (lane < 2) v5 = __ldg(&src[lane + 160]);
        }

        // independent long-latency load: this row's true class
        const int row = t * WROWS + r;
        int tc = (int)g_tc[row];

        const float* rp = buf + r * C;
        float s0, s1, s2, s3;
        s0 = ex2f(rp[sub]      * L2E);
        s1 = ex2f(rp[sub + 4]  * L2E);
        s2 = ex2f(rp[sub + 8]  * L2E);
        s3 = ex2f(rp[sub + 12] * L2E);
        s0 += ex2f(rp[sub + 16] * L2E);
        s1 += ex2f(rp[sub + 20] * L2E);
        s2 += ex2f(rp[sub + 24] * L2E);
        s3 += ex2f(rp[sub + 28] * L2E);
        s0 += ex2f(rp[sub + 32] * L2E);
        s1 += ex2f(rp[sub + 36] * L2E);
        s2 += ex2f(rp[sub + 40] * L2E);
        s3 += ex2f(rp[sub + 44] * L2E);
        s0 += ex2f(rp[sub + 48] * L2E);
        s1 += ex2f(rp[sub + 52] * L2E);
        s2 += ex2f(rp[sub + 56] * L2E);
        s3 += ex2f(rp[sub + 60] * L2E);
        s0 += ex2f(rp[sub + 64] * L2E);
        s1 += ex2f(rp[sub + 68] * L2E);
        s2 += ex2f(rp[sub + 72] * L2E);
        s3 += ex2f(rp[sub + 76] * L2E);
        float s = (s0 + s1) + (s2 + s3);
        if (sub == 0) s += ex2f(rp[80] * L2E);
        s += __shfl_xor_sync(0xffffffffu, s, 1);
        s += __shfl_xor_sync(0xffffffffu, s, 2);

        if (sub == 0) {
            const int b = row / P;
            float conf = lg2f(s) * LN2 - rp[tc];   // -(log_softmax[tc]) >= 0
            bool pos = tc > 0;
            g_conf_neg[row] = pos ? 0.0f : conf;
            if (pos) {
                atomicAdd(&g_conf_pos[b], (double)conf);
                atomicAdd(&g_n_pos[b], 1);
                float4 bx = locs[row];
                float iw = fmaxf(bx.z - bx.x, 0.0f);
                float ih = fmaxf(bx.w - bx.y, 0.0f);
                float inter = iw * ih;
                float area = (bx.z - bx.x) * (bx.w - bx.y);
                float iou = __fdividef(inter, area + area - inter + EPSF);
                float dious = fminf(fmaxf(iou, -1.0f), 1.0f);  // inter_diag==0 exactly
                atomicAdd(&g_loc_pb[b], (double)(1.0f - dious));
            }
        }
        __syncwarp();   // all lanes done reading buf before next iter's stores
    }
}

// ---------------- K4: per-batch top-k sum, 3-pass (11/11/10-bit) radix select ----------------
#define TKT 1024
__global__ void __launch_bounds__(TKT)
k_topk(float* __restrict__ out) {
    const int b    = blockIdx.x;
    const int tid  = threadIdx.x;
    const int lane = tid & 31;
    const int wid  = tid >> 5;

    __shared__ unsigned int sv[P];     // 34928 B
    __shared__ int hist[2048];         // 8192 B
    __shared__ int wtot[32], wsuf[33];
    __shared__ int s_bin, s_kk;
    __shared__ int s_last;

    {
        const uint4* src = (const uint4*)(g_conf_neg + b * P);
        uint4* dst = (uint4*)sv;
        for (int i = tid; i < P / 4; i += TKT) dst[i] = src[i];
    }
    __syncthreads();

    long long k = 3LL * (long long)g_n_pos[b];
    double result = 0.0;

    if (k >= P) {
        double sum = 0.0;
        for (int p = tid; p < P; p += TKT) sum += (double)__uint_as_float(sv[p]);
        result = blockReduceSumD(sum);
    } else if (k > 0) {
        unsigned int prefix = 0;
        int kk = (int)k;
        #pragma unroll
        for (int pass = 0; pass < 3; pass++) {
            const int sh   = (pass == 0) ? 21 : (pass == 1) ? 10 : 0;
            const int bits = (pass == 2) ? 10 : 11;
            const unsigned int dmask = (1u << bits) - 1u;
            hist[tid] = 0; hist[tid + 1024] = 0;
            __syncthreads();
            for (int base = 0; base < P; base += TKT) {
                int p = base + tid;
                bool in = p < P;
                unsigned int v = in ? sv[p] : 0u;
                bool match = in && (pass == 0 || (v >> (sh + bits)) == prefix);
                unsigned int act = __ballot_sync(0xffffffffu, match);
                if (match) {
                    unsigned int bin = (v >> sh) & dmask;
                    unsigned int peers = __match_any_sync(act, bin);
                    if ((__ffs(peers) - 1) == lane)
                        atomicAdd(&hist[bin], (int)__popc(peers));
                }
            }
            __syncthreads();
            // block-wide suffix scan: thread owns bins 2*tid, 2*tid+1
            int h_lo = hist[2 * tid], h_hi = hist[2 * tid + 1];
            int tot = h_lo + h_hi;
            int v = tot;
            #pragma unroll
            for (int o = 1; o < 32; o <<= 1) {
                int u = __shfl_down_sync(0xffffffffu, v, o);
                if (lane + o < 32) v += u;
            }
            if (lane == 0) wtot[wid] = v;
            __syncthreads();
            if (wid == 0) {
                int x = wtot[lane];
                #pragma unroll
                for (int o = 1; o < 32; o <<= 1) {
                    int u = __shfl_down_sync(0xffffffffu, x, o);
                    if (lane + o < 32) x += u;
                }
                wsuf[lane] = x;
                if (lane == 0) wsuf[32] = 0;
            }
            __syncthreads();
            int after = (v - tot) + wsuf[wid + 1];   // strictly after this thread
            int cge0 = tot + after;
            int cge1 = h_hi + after;
            int cge2 = after;
            if (cge0 >= kk && cge1 < kk) { s_bin = 2 * tid;     s_kk = kk - cge1; }
            if (cge1 >= kk && cge2 < kk) { s_bin = 2 * tid + 1; s_kk = kk - cge2; }
            __syncthreads();
            prefix = (prefix << bits) | (unsigned int)s_bin;
            kk = s_kk;
            __syncthreads();
        }
        unsigned int thr = prefix;   // exact k-th largest bit pattern
        double sum = 0.0;
        for (int p = tid; p < P; p += TKT) {
            unsigned int v = sv[p];
            if (v > thr) sum += (double)__uint_as_float(v);
        }
        result = blockReduceSumD(sum);
        if (tid == 0) result += (double)kk * (double)__uint_as_float(thr);
    }
    if (tid == 0) g_hard_pb[b] = result;

    // ---- fused final: last block combines everything ----
    __threadfence();
    if (tid == 0) {
        unsigned int t = atomicAdd(&g_done, 1u);
        s_last = (t == B - 1u) ? 1 : 0;
    }
    __syncthreads();
    if (s_last) {
        double cp = 0.0, hs = 0.0, ls = 0.0;
        long long np = 0;
        if (tid < B) {
            cp = g_conf_pos[tid];
            hs = g_hard_pb[tid];
            ls = g_loc_pb[tid];
            np = g_n_pos[tid];
        }
        double cps = blockReduceSumD(cp);
        double hss = blockReduceSumD(hs);
        double lss = blockReduceSumD(ls);
        double nps = blockReduceSumD((double)np);
        if (tid == 0) {
            float conf_loss = (float)((hss + cps) / nps);
            float loc_loss  = (float)(lss / fmax(nps, 1.0));
            out[0] = conf_loss + loc_loss;  // ALPHA = 1.0
        }
    }
}

// ---------------- launch ----------------
extern "C" void kernel_launch(void* const* d_in, const int* in_sizes, int n_in,
                              void* d_out, int out_size) {
    const float* locs   = (const float*)d_in[0];  // [B,P,4]
    const float* scores = (const float*)d_in[1];  // [B,P,C]
    const float* boxes  = (const float*)d_in[2];  // [B,M,4]
    const int*   labels = (const int*)  d_in[3];  // [B,M]
    const float* priors = (const float*)d_in[4];  // [P,4]
    float* out = (float*)d_out;

    cudaFuncSetAttribute(k_conf, cudaFuncAttributeMaxDynamicSharedMemorySize, WSMEM);

    k_obj<<<OBJ_GRID, OBJ_TPB>>>((const float4*)boxes, (const float4*)priors);
    k_match<<<MGRID, MT>>>((const float4*)boxes, labels, (const float4*)priors);
    k_conf<<<WGRID, CW * 32, WSMEM>>>((const float4*)scores, (const float4*)locs);
    k_topk<<<B, TKT>>>(out);
}

// round 15
// speedup vs baseline: 1.0507x; 1.0216x over previous
#include <cuda_runtime.h>
#include <math.h>

#define B 64
#define P 8732
#define M 16
#define C 81
#define EPSF 1e-7f
#define L2E 1.4426950408889634f
#define LN2 0.6931471805599453f

// ---------------- device scratch ----------------
__device__ __align__(16) float g_conf_neg[B * P];
__device__ unsigned char       g_tc[B * P];        // PLAIN matcher tc (pre-override)
__device__ unsigned long long  g_best[B * M];      // packed (iou_bits<<32)|~prior_idx
__device__ unsigned int        g_force[B * M];     // (prior<<8)|(j+1), 0 = none
__device__ int                 g_n_pos[B];
__device__ double              g_conf_pos[B];
__device__ double              g_loc_pb[B];
__device__ double              g_hard_pb[B];
__device__ unsigned int        g_done;
__device__ unsigned int        g_obj_done;

// ---------------- helpers ----------------
__device__ __forceinline__ float ex2f(float x) {
    float y; asm("ex2.approx.ftz.f32 %0, %1;" : "=f"(y) : "f"(x)); return y;
}
__device__ __forceinline__ float lg2f(float x) {
    float y; asm("lg2.approx.ftz.f32 %0, %1;" : "=f"(y) : "f"(x)); return y;
}

__device__ __forceinline__ double blockReduceSumD(double v) {
    __shared__ double sh[32];
    int lane = threadIdx.x & 31, wid = threadIdx.x >> 5;
    #pragma unroll
    for (int o = 16; o; o >>= 1) v += __shfl_down_sync(0xffffffffu, v, o);
    if (lane == 0) sh[wid] = v;
    __syncthreads();
    int nw = (blockDim.x + 31) >> 5;
    v = (threadIdx.x < (unsigned)nw) ? sh[threadIdx.x] : 0.0;
    if (wid == 0) {
        #pragma unroll
        for (int o = 16; o; o >>= 1) v += __shfl_down_sync(0xffffffffu, v, o);
    }
    __syncthreads();
    return v;  // valid in thread 0
}

// ---------------- K-obj (side stream): per-object best prior; last block builds g_force ----------------
#define OBJ_TPB    256
#define OBJ_GRID   (B * M)           // 1024 blocks
__global__ void __launch_bounds__(OBJ_TPB)
k_obj(const float4* __restrict__ boxes,
      const float4* __restrict__ priors) {
    const int bm   = blockIdx.x;
    const int tid  = threadIdx.x;
    const int lane = tid & 31;
    const int wid  = tid >> 5;

    __shared__ unsigned long long wred[OBJ_TPB / 32];
    __shared__ int s_last;

    float4 bx = __ldg(&boxes[bm]);
    float areab = (bx.z - bx.x) * (bx.w - bx.y);

    unsigned long long vmax = 0ull;
    for (int p = tid; p < P; p += OBJ_TPB) {
        float4 pc = __ldg(&priors[p]);
        float px0 = pc.x - pc.z * 0.5f;
        float py0 = pc.y - pc.w * 0.5f;
        float px1 = pc.x + pc.z * 0.5f;
        float py1 = pc.y + pc.w * 0.5f;
        float areap = (px1 - px0) * (py1 - py0);
        float iw = fmaxf(fminf(bx.z, px1) - fmaxf(bx.x, px0), 0.0f);
        float ih = fmaxf(fminf(bx.w, py1) - fmaxf(bx.y, py0), 0.0f);
        float inter = iw * ih;
        float iou = __fdividef(inter, areab + areap - inter);
        unsigned long long pk =
            ((unsigned long long)__float_as_uint(iou) << 32) |
            (unsigned long long)(~(unsigned int)p);      // ties -> smallest p
        if (pk > vmax) vmax = pk;
    }
    #pragma unroll
    for (int o = 16; o; o >>= 1) {
        unsigned long long u = __shfl_down_sync(0xffffffffu, vmax, o);
        if (u > vmax) vmax = u;
    }
    if (lane == 0) wred[wid] = vmax;
    __syncthreads();
    if (tid == 0) {
        unsigned long long v = wred[0];
        #pragma unroll
        for (int w = 1; w < OBJ_TPB / 32; w++)
            if (wred[w] > v) v = wred[w];
        g_best[bm] = v;
    }

    __threadfence();
    if (tid == 0) {
        unsigned int t = atomicAdd(&g_obj_done, 1u);
        s_last = (t == OBJ_GRID - 1u) ? 1 : 0;
    }
    __syncthreads();
    if (s_last) {
        if (tid < B) {
            const int bb = tid;
            int j = -1;
            #pragma unroll
            for (int mm = 0; mm < M; mm++) {
                unsigned long long v = g_best[bb * M + mm];
                unsigned int e = 0u;
                if (v >> 32) {
                    j++;
                    unsigned int pp = ~(unsigned int)(v & 0xffffffffull);
                    e = (pp << 8) | (unsigned int)(j + 1);
                }
                g_force[bb * M + mm] = e;
            }
        }
        if (tid == 0) g_obj_done = 0u;
        __threadfence();
    }
}

// ---------------- K-match (main): per-prior PLAIN matcher -> g_tc; block 0 inits accumulators ----------------
#define MT        256
#define MCHUNK    ((P + MT - 1) / MT)    // 35
#define MGRID     (B * MCHUNK)           // 2240
__global__ void __launch_bounds__(MT)
k_match(const float4* __restrict__ boxes,
        const int*    __restrict__ labels,
        const float4* __restrict__ priors) {
    const int b     = blockIdx.x / MCHUNK;
    const int chunk = blockIdx.x % MCHUNK;
    const int tid   = threadIdx.x;
    const int p     = chunk * MT + tid;
    const bool valid = p < P;

    if (blockIdx.x == 0) {
        if (tid < B) { g_conf_pos[tid] = 0.0; g_loc_pb[tid] = 0.0; g_n_pos[tid] = 0; }
        if (tid == B) g_done = 0u;
    }

    __shared__ float4        sbox[M];
    __shared__ float         sarea[M];
    __shared__ unsigned char slab[M];
    if (tid < M) {
        float4 bx = boxes[b * M + tid];
        sbox[tid]  = bx;
        sarea[tid] = (bx.z - bx.x) * (bx.w - bx.y);
        slab[tid]  = (unsigned char)labels[b * M + tid];
    }
    __syncthreads();

    float px0 = 0.f, py0 = 0.f, px1 = 0.f, py1 = 0.f, areap = 0.f;
    if (valid) {
        float4 pc = priors[p];
        px0 = pc.x - pc.z * 0.5f;
        py0 = pc.y - pc.w * 0.5f;
        px1 = pc.x + pc.z * 0.5f;
        py1 = pc.y + pc.w * 0.5f;
        areap = (px1 - px0) * (py1 - py0);
    }

    float bv = -1.0f; int bm = 0;
    #pragma unroll
    for (int m = 0; m < M; m++) {
        float4 bx = sbox[m];
        float iw = fmaxf(fminf(bx.z, px1) - fmaxf(bx.x, px0), 0.0f);
        float ih = fmaxf(fminf(bx.w, py1) - fmaxf(bx.y, py0), 0.0f);
        float inter = iw * ih;
        float iou = __fdividef(inter, sarea[m] + areap - inter);
        if (iou > bv) { bv = iou; bm = m; }   // first-max over m (same math as reference)
    }
    if (valid)
        g_tc[b * P + p] = (bv < 0.5f) ? (unsigned char)0 : slab[bm];
}

// ---------------- K-conf (main): CE loss over PLAIN tc; LDG.128->regs->STS.128 staging ----------------
#define CW        8
#define WROWS     8
#define WTILE_F   (WROWS * C)         // 648 floats
#define WTILE_V4  (WTILE_F / 4)       // 162
#define WNT       (B * P / WROWS)     // 69856 exact
#define WGRID     592
#define WSMEM     (CW * WTILE_F * 4)  // 20736 B

__global__ void __launch_bounds__(CW * 32)
k_conf(const float4* __restrict__ scores4,
       const float4* __restrict__ locs) {
    extern __shared__ float sm[];
    const int wid  = threadIdx.x >> 5;
    const int lane = threadIdx.x & 31;
    const int sub  = lane & 3;
    const int r    = lane >> 2;
    float* buf = sm + wid * WTILE_F;

    const int gw = blockIdx.x * CW + wid;
    const int nw = WGRID * CW;

    float4 v0, v1, v2, v3, v4, v5;
    v5 = make_float4(0.f, 0.f, 0.f, 0.f);
    int t = gw;
    if (t < WNT) {
        const float4* src = scores4 + (size_t)t * WTILE_V4;
        v0 = __ldg(&src[lane]);
        v1 = __ldg(&src[lane + 32]);
        v2 = __ldg(&src[lane + 64]);
        v3 = __ldg(&src[lane + 96]);
        v4 = __ldg(&src[lane + 128]);
        if (lane < 2) v5 = __ldg(&src[lane + 160]);
    }

    for (; t < WNT; t += nw) {
        float4* dst = (float4*)buf;
        dst[lane]       = v0;
        dst[lane + 32]  = v1;
        dst[lane + 64]  = v2;
        dst[lane + 96]  = v3;
        dst[lane + 128] = v4;
        if (lane < 2) dst[lane + 160] = v5;
        __syncwarp();

        int tn = t + nw;
        if (tn < WNT) {
            const float4* src = scores4 + (size_t)tn * WTILE_V4;
            v0 = __ldg(&src[lane]);
            v1 = __ldg(&src[lane + 32]);
            v2 = __ldg(&src[lane + 64]);
            v3 = __ldg(&src[lane + 96]);
            v4 = __ldg(&src[lane + 128]);
            if (lane < 2) v5 = __ldg(&src[lane + 160]);
        }

        const int row = t * WROWS + r;
        int tc = (int)g_tc[row];

        const float* rp = buf + r * C;
        float s0, s1, s2, s3;
        s0 = ex2f(rp[sub]      * L2E);
        s1 = ex2f(rp[sub + 4]  * L2E);
        s2 = ex2f(rp[sub + 8]  * L2E);
        s3 = ex2f(rp[sub + 12] * L2E);
        s0 += ex2f(rp[sub + 16] * L2E);
        s1 += ex2f(rp[sub + 20] * L2E);
        s2 += ex2f(rp[sub + 24] * L2E);
        s3 += ex2f(rp[sub + 28] * L2E);
        s0 += ex2f(rp[sub + 32] * L2E);
        s1 += ex2f(rp[sub + 36] * L2E);
        s2 += ex2f(rp[sub + 40] * L2E);
        s3 += ex2f(rp[sub + 44] * L2E);
        s0 += ex2f(rp[sub + 48] * L2E);
        s1 += ex2f(rp[sub + 52] * L2E);
        s2 += ex2f(rp[sub + 56] * L2E);
        s3 += ex2f(rp[sub + 60] * L2E);
        s0 += ex2f(rp[sub + 64] * L2E);
        s1 += ex2f(rp[sub + 68] * L2E);
        s2 += ex2f(rp[sub + 72] * L2E);
        s3 += ex2f(rp[sub + 76] * L2E);
        float s = (s0 + s1) + (s2 + s3);
        if (sub == 0) s += ex2f(rp[80] * L2E);
        s += __shfl_xor_sync(0xffffffffu, s, 1);
        s += __shfl_xor_sync(0xffffffffu, s, 2);

        if (sub == 0) {
            const int b = row / P;
            float conf = lg2f(s) * LN2 - rp[tc];
            bool pos = tc > 0;
            g_conf_neg[row] = pos ? 0.0f : conf;
            if (pos) {
                atomicAdd(&g_conf_pos[b], (double)conf);
                atomicAdd(&g_n_pos[b], 1);
                float4 bx = locs[row];
                float iw = fmaxf(bx.z - bx.x, 0.0f);
                float ih = fmaxf(bx.w - bx.y, 0.0f);
                float inter = iw * ih;
                float area = (bx.z - bx.x) * (bx.w - bx.y);
                float iou = __fdividef(inter, area + area - inter + EPSF);
                float dious = fminf(fmaxf(iou, -1.0f), 1.0f);
                atomicAdd(&g_loc_pb[b], (double)(1.0f - dious));
            }
        }
        __syncwarp();
    }
}

// ---------------- K-fix: patch the <=1024 overridden rows (exact same float op order as k_conf) ----------------
__global__ void __launch_bounds__(64)
k_fix(const float* __restrict__ scores,
      const float4* __restrict__ locs,
      const int*    __restrict__ labels) {
    const int b   = blockIdx.x;
    const int tid = threadIdx.x;          // 64 threads: 16 groups of 4
    const int m   = tid >> 2;
    const int sub = tid & 3;
    const unsigned int gmask = 0xFu << ((tid & 31) & ~3);

    unsigned int e = g_force[b * M + m];
    float s = 0.0f;
    int p = 0, j = 0, row = 0;
    const float* rp = scores;
    if (e) {
        p   = (int)(e >> 8);
        j   = (int)(e & 0xffu) - 1;
        row = b * P + p;
        rp  = scores + (size_t)row * C;
        float s0, s1, s2, s3;
        s0 = ex2f(__ldg(&rp[sub])      * L2E);
        s1 = ex2f(__ldg(&rp[sub + 4])  * L2E);
        s2 = ex2f(__ldg(&rp[sub + 8])  * L2E);
        s3 = ex2f(__ldg(&rp[sub + 12]) * L2E);
        s0 += ex2f(__ldg(&rp[sub + 16]) * L2E);
        s1 += ex2f(__ldg(&rp[sub + 20]) * L2E);
        s2 += ex2f(__ldg(&rp[sub + 24]) * L2E);
        s3 += ex2f(__ldg(&rp[sub + 28]) * L2E);
        s0 += ex2f(__ldg(&rp[sub + 32]) * L2E);
        s1 += ex2f(__ldg(&rp[sub + 36]) * L2E);
        s2 += ex2f(__ldg(&rp[sub + 40]) * L2E);
        s3 += ex2f(__ldg(&rp[sub + 44]) * L2E);
        s0 += ex2f(__ldg(&rp[sub + 48]) * L2E);
        s1 += ex2f(__ldg(&rp[sub + 52]) * L2E);
        s2 += ex2f(__ldg(&rp[sub + 56]) * L2E);
        s3 += ex2f(__ldg(&rp[sub + 60]) * L2E);
        s0 += ex2f(__ldg(&rp[sub + 64]) * L2E);
        s1 += ex2f(__ldg(&rp[sub + 68]) * L2E);
        s2 += ex2f(__ldg(&rp[sub + 72]) * L2E);
        s3 += ex2f(__ldg(&rp[sub + 76]) * L2E);
        s = (s0 + s1) + (s2 + s3);
        if (sub == 0) s += ex2f(__ldg(&rp[80]) * L2E);
    }
    // combine the 4 group lanes exactly like k_conf's shfl_xor 1,2
    s += __shfl_xor_sync(gmask, s, 1);
    s += __shfl_xor_sync(gmask, s, 2);

    if (e && sub == 0) {
        int old_tc = (int)g_tc[row];
        int new_tc = __ldg(&labels[b * M + j]);    // faithful j_idx: filtered index
        float lse = lg2f(s) * LN2;
        float conf_old = lse - __ldg(&rp[old_tc]); // exactly what k_conf computed
        float conf_new = lse - __ldg(&rp[new_tc]);
        if (old_tc > 0) {
            // row was already positive: only the CE value changes
            atomicAdd(&g_conf_pos[b], (double)conf_new - (double)conf_old);
        } else {
            // row flips negative -> positive
            g_conf_neg[row] = 0.0f;
            atomicAdd(&g_conf_pos[b], (double)conf_new);
            atomicAdd(&g_n_pos[b], 1);
            float4 bx = __ldg(&locs[row]);
            float iw = fmaxf(bx.z - bx.x, 0.0f);
            float ih = fmaxf(bx.w - bx.y, 0.0f);
            float inter = iw * ih;
            float area = (bx.z - bx.x) * (bx.w - bx.y);
            float iou = __fdividef(inter, area + area - inter + EPSF);
            float dious = fminf(fmaxf(iou, -1.0f), 1.0f);
            atomicAdd(&g_loc_pb[b], (double)(1.0f - dious));
        }
    }
}

// ---------------- K-topk: per-batch top-k sum, 3-pass radix select + fused final ----------------
#define TKT 1024
__global__ void __launch_bounds__(TKT)
k_topk(float* __restrict__ out) {
    const int b    = blockIdx.x;
    const int tid  = threadIdx.x;
    const int lane = tid & 31;
    const int wid  = tid >> 5;

    __shared__ unsigned int sv[P];
    __shared__ int hist[2048];
    __shared__ int wtot[32], wsuf[33];
    __shared__ int s_bin, s_kk;
    __shared__ int s_last;

    {
        const uint4* src = (const uint4*)(g_conf_neg + b * P);
        uint4* dst = (uint4*)sv;
        for (int i = tid; i < P / 4; i += TKT) dst[i] = src[i];
    }
    __syncthreads();

    long long k = 3LL * (long long)g_n_pos[b];
    double result = 0.0;

    if (k >= P) {
        double sum = 0.0;
        for (int p = tid; p < P; p += TKT) sum += (double)__uint_as_float(sv[p]);
        result = blockReduceSumD(sum);
    } else if (k > 0) {
        unsigned int prefix = 0;
        int kk = (int)k;
        #pragma unroll
        for (int pass = 0; pass < 3; pass++) {
            const int sh   = (pass == 0) ? 21 : (pass == 1) ? 10 : 0;
            const int bits = (pass == 2) ? 10 : 11;
            const unsigned int dmask = (1u << bits) - 1u;
            hist[tid] = 0; hist[tid + 1024] = 0;
            __syncthreads();
            for (int base = 0; base < P; base += TKT) {
                int p = base + tid;
                bool in = p < P;
                unsigned int v = in ? sv[p] : 0u;
                bool match = in && (pass == 0 || (v >> (sh + bits)) == prefix);
                unsigned int act = __ballot_sync(0xffffffffu, match);
                if (match) {
                    unsigned int bin = (v >> sh) & dmask;
                    unsigned int peers = __match_any_sync(act, bin);
                    if ((__ffs(peers) - 1) == lane)
                        atomicAdd(&hist[bin], (int)__popc(peers));
                }
            }
            __syncthreads();
            int h_lo = hist[2 * tid], h_hi = hist[2 * tid + 1];
            int tot = h_lo + h_hi;
            int v = tot;
            #pragma unroll
            for (int o = 1; o < 32; o <<= 1) {
                int u = __shfl_down_sync(0xffffffffu, v, o);
                if (lane + o < 32) v += u;
            }
            if (lane == 0) wtot[wid] = v;
            __syncthreads();
            if (wid == 0) {
                int x = wtot[lane];
                #pragma unroll
                for (int o = 1; o < 32; o <<= 1) {
                    int u = __shfl_down_sync(0xffffffffu, x, o);
                    if (lane + o < 32) x += u;
                }
                wsuf[lane] = x;
                if (lane == 0) wsuf[32] = 0;
            }
            __syncthreads();
            int after = (v - tot) + wsuf[wid + 1];
            int cge0 = tot + after;
            int cge1 = h_hi + after;
            int cge2 = after;
            if (cge0 >= kk && cge1 < kk) { s_bin = 2 * tid;     s_kk = kk - cge1; }
            if (cge1 >= kk && cge2 < kk) { s_bin = 2 * tid + 1; s_kk = kk - cge2; }
            __syncthreads();
            prefix = (prefix << bits) | (unsigned int)s_bin;
            kk = s_kk;
            __syncthreads();
        }
        unsigned int thr = prefix;
        double sum = 0.0;
        for (int p = tid; p < P; p += TKT) {
            unsigned int v = sv[p];
            if (v > thr) sum += (double)__uint_as_float(v);
        }
        result = blockReduceSumD(sum);
        if (tid == 0) result += (double)kk * (double)__uint_as_float(thr);
    }
    if (tid == 0) g_hard_pb[b] = result;

    __threadfence();
    if (tid == 0) {
        unsigned int t = atomicAdd(&g_done, 1u);
        s_last = (t == B - 1u) ? 1 : 0;
    }
    __syncthreads();
    if (s_last) {
        double cp = 0.0, hs = 0.0, ls = 0.0;
        long long np = 0;
        if (tid < B) {
            cp = g_conf_pos[tid];
            hs = g_hard_pb[tid];
            ls = g_loc_pb[tid];
            np = g_n_pos[tid];
        }
        double cps = blockReduceSumD(cp);
        double hss = blockReduceSumD(hs);
        double lss = blockReduceSumD(ls);
        double nps = blockReduceSumD((double)np);
        if (tid == 0) {
            float conf_loss = (float)((hss + cps) / nps);
            float loc_loss  = (float)(lss / fmax(nps, 1.0));
            out[0] = conf_loss + loc_loss;  // ALPHA = 1.0
        }
    }
}

// ---------------- launch: fork k_obj onto side stream, join before k_fix ----------------
extern "C" void kernel_launch(void* const* d_in, const int* in_sizes, int n_in,
                              void* d_out, int out_size) {
    const float* locs   = (const float*)d_in[0];  // [B,P,4]
    const float* scores = (const float*)d_in[1];  // [B,P,C]
    const float* boxes  = (const float*)d_in[2];  // [B,M,4]
    const int*   labels = (const int*)  d_in[3];  // [B,M]
    const float* priors = (const float*)d_in[4];  // [P,4]
    float* out = (float*)d_out;

    static bool init_done = false;
    static cudaStream_t s2 = nullptr;
    static cudaEvent_t ev_fork = nullptr, ev_join = nullptr;
    if (!init_done) {
        init_done = true;   // one-time host-side handle creation (first call = correctness run)
        if (cudaStreamCreateWithFlags(&s2, cudaStreamNonBlocking) != cudaSuccess) s2 = nullptr;
        if (s2) {
            if (cudaEventCreateWithFlags(&ev_fork, cudaEventDisableTiming) != cudaSuccess ||
                cudaEventCreateWithFlags(&ev_join, cudaEventDisableTiming) != cudaSuccess) {
                s2 = nullptr;
            }
        }
        cudaFuncSetAttribute(k_conf, cudaFuncAttributeMaxDynamicSharedMemorySize, WSMEM);
    }

    if (s2) {
        // fork: k_obj runs concurrently with k_match + k_conf
        cudaEventRecord(ev_fork, 0);
        cudaStreamWaitEvent(s2, ev_fork, 0);
        k_obj<<<OBJ_GRID, OBJ_TPB, 0, s2>>>((const float4*)boxes, (const float4*)priors);
        cudaEventRecord(ev_join, s2);

        k_match<<<MGRID, MT>>>((const float4*)boxes, labels, (const float4*)priors);
        k_conf<<<WGRID, CW * 32, WSMEM>>>((const float4*)scores, (const float4*)locs);

        cudaStreamWaitEvent(0, ev_join, 0);   // join before patching
    } else {
        // fallback: fully sequential on the default stream
        k_obj<<<OBJ_GRID, OBJ_TPB>>>((const float4*)boxes, (const float4*)priors);
        k_match<<<MGRID, MT>>>((const float4*)boxes, labels, (const float4*)priors);
        k_conf<<<WGRID, CW * 32, WSMEM>>>((const float4*)scores, (const float4*)locs);
    }

    k_fix<<<B, 64>>>(scores, (const float4*)locs, labels);
    k_topk<<<B, TKT>>>(out);
}

// round 16
// speedup vs baseline: 1.1042x; 1.0509x over previous
#include <cuda_runtime.h>
#include <math.h>

#define B 64
#define P 8732
#define M 16
#define C 81
#define EPSF 1e-7f
#define L2E 1.4426950408889634f
#define LN2 0.6931471805599453f

// ---------------- device scratch ----------------
__device__ __align__(16) float g_conf_neg[B * P];
__device__ unsigned char       g_tc[B * P];        // PLAIN matcher tc (pre-override)
__device__ unsigned long long  g_best[B * M];      // packed (iou_bits<<32)|~prior_idx
__device__ unsigned int        g_force[B * M];     // (prior<<8)|(j+1), 0 = none
__device__ int                 g_n_pos[B];
__device__ double              g_conf_pos[B];
__device__ double              g_loc_pb[B];
__device__ double              g_hard_pb[B];
__device__ unsigned int        g_done;
__device__ unsigned int        g_obj_done;

// ---------------- helpers ----------------
__device__ __forceinline__ float ex2f(float x) {
    float y; asm("ex2.approx.ftz.f32 %0, %1;" : "=f"(y) : "f"(x)); return y;
}
__device__ __forceinline__ float lg2f(float x) {
    float y; asm("lg2.approx.ftz.f32 %0, %1;" : "=f"(y) : "f"(x)); return y;
}

__device__ __forceinline__ double blockReduceSumD(double v) {
    __shared__ double sh[32];
    int lane = threadIdx.x & 31, wid = threadIdx.x >> 5;
    #pragma unroll
    for (int o = 16; o; o >>= 1) v += __shfl_down_sync(0xffffffffu, v, o);
    if (lane == 0) sh[wid] = v;
    __syncthreads();
    int nw = (blockDim.x + 31) >> 5;
    v = (threadIdx.x < (unsigned)nw) ? sh[threadIdx.x] : 0.0;
    if (wid == 0) {
        #pragma unroll
        for (int o = 16; o; o >>= 1) v += __shfl_down_sync(0xffffffffu, v, o);
    }
    __syncthreads();
    return v;  // valid in thread 0
}

// ---------------- K-obj (side stream): per-object best prior; last block builds g_force ----------------
#define OBJ_TPB    256
#define OBJ_GRID   (B * M)           // 1024 blocks
__global__ void __launch_bounds__(OBJ_TPB)
k_obj(const float4* __restrict__ boxes,
      const float4* __restrict__ priors) {
    const int bm   = blockIdx.x;
    const int tid  = threadIdx.x;
    const int lane = tid & 31;
    const int wid  = tid >> 5;

    __shared__ unsigned long long wred[OBJ_TPB / 32];
    __shared__ int s_last;

    float4 bx = __ldg(&boxes[bm]);
    float areab = (bx.z - bx.x) * (bx.w - bx.y);

    unsigned long long vmax = 0ull;
    for (int p = tid; p < P; p += OBJ_TPB) {
        float4 pc = __ldg(&priors[p]);
        float px0 = pc.x - pc.z * 0.5f;
        float py0 = pc.y - pc.w * 0.5f;
        float px1 = pc.x + pc.z * 0.5f;
        float py1 = pc.y + pc.w * 0.5f;
        float areap = (px1 - px0) * (py1 - py0);
        float iw = fmaxf(fminf(bx.z, px1) - fmaxf(bx.x, px0), 0.0f);
        float ih = fmaxf(fminf(bx.w, py1) - fmaxf(bx.y, py0), 0.0f);
        float inter = iw * ih;
        float iou = __fdividef(inter, areab + areap - inter);
        unsigned long long pk =
            ((unsigned long long)__float_as_uint(iou) << 32) |
            (unsigned long long)(~(unsigned int)p);      // ties -> smallest p
        if (pk > vmax) vmax = pk;
    }
    #pragma unroll
    for (int o = 16; o; o >>= 1) {
        unsigned long long u = __shfl_down_sync(0xffffffffu, vmax, o);
        if (u > vmax) vmax = u;
    }
    if (lane == 0) wred[wid] = vmax;
    __syncthreads();
    if (tid == 0) {
        unsigned long long v = wred[0];
        #pragma unroll
        for (int w = 1; w < OBJ_TPB / 32; w++)
            if (wred[w] > v) v = wred[w];
        g_best[bm] = v;
    }

    __threadfence();
    if (tid == 0) {
        unsigned int t = atomicAdd(&g_obj_done, 1u);
        s_last = (t == OBJ_GRID - 1u) ? 1 : 0;
    }
    __syncthreads();
    if (s_last) {
        if (tid < B) {
            const int bb = tid;
            int j = -1;
            #pragma unroll
            for (int mm = 0; mm < M; mm++) {
                unsigned long long v = g_best[bb * M + mm];
                unsigned int e = 0u;
                if (v >> 32) {
                    j++;
                    unsigned int pp = ~(unsigned int)(v & 0xffffffffull);
                    e = (pp << 8) | (unsigned int)(j + 1);
                }
                g_force[bb * M + mm] = e;
            }
        }
        if (tid == 0) g_obj_done = 0u;
        __threadfence();
    }
}

// ---------------- K-match (main): per-prior PLAIN matcher -> g_tc; block 0 inits accumulators ----------------
#define MT        256
#define MCHUNK    ((P + MT - 1) / MT)    // 35
#define MGRID     (B * MCHUNK)           // 2240
__global__ void __launch_bounds__(MT)
k_match(const float4* __restrict__ boxes,
        const int*    __restrict__ labels,
        const float4* __restrict__ priors) {
    const int b     = blockIdx.x / MCHUNK;
    const int chunk = blockIdx.x % MCHUNK;
    const int tid   = threadIdx.x;
    const int p     = chunk * MT + tid;
    const bool valid = p < P;

    if (blockIdx.x == 0) {
        if (tid < B) { g_conf_pos[tid] = 0.0; g_loc_pb[tid] = 0.0; g_n_pos[tid] = 0; }
        if (tid == B) g_done = 0u;
    }

    __shared__ float4        sbox[M];
    __shared__ float         sarea[M];
    __shared__ unsigned char slab[M];
    if (tid < M) {
        float4 bx = boxes[b * M + tid];
        sbox[tid]  = bx;
        sarea[tid] = (bx.z - bx.x) * (bx.w - bx.y);
        slab[tid]  = (unsigned char)labels[b * M + tid];
    }
    __syncthreads();

    float px0 = 0.f, py0 = 0.f, px1 = 0.f, py1 = 0.f, areap = 0.f;
    if (valid) {
        float4 pc = priors[p];
        px0 = pc.x - pc.z * 0.5f;
        py0 = pc.y - pc.w * 0.5f;
        px1 = pc.x + pc.z * 0.5f;
        py1 = pc.y + pc.w * 0.5f;
        areap = (px1 - px0) * (py1 - py0);
    }

    float bv = -1.0f; int bm = 0;
    #pragma unroll
    for (int m = 0; m < M; m++) {
        float4 bx = sbox[m];
        float iw = fmaxf(fminf(bx.z, px1) - fmaxf(bx.x, px0), 0.0f);
        float ih = fmaxf(fminf(bx.w, py1) - fmaxf(bx.y, py0), 0.0f);
        float inter = iw * ih;
        float iou = __fdividef(inter, sarea[m] + areap - inter);
        if (iou > bv) { bv = iou; bm = m; }   // first-max over m (same math as reference)
    }
    if (valid)
        g_tc[b * P + p] = (bv < 0.5f) ? (unsigned char)0 : slab[bm];
}

// ---------------- K-conf (main): CE loss over PLAIN tc; streaming LDG.128->regs->STS.128 ----------------
#define CW        8
#define WROWS     8
#define WTILE_F   (WROWS * C)         // 648 floats
#define WTILE_V4  (WTILE_F / 4)       // 162
#define WNT       (B * P / WROWS)     // 69856 exact
#define WGRID     592
#define WSMEM     (CW * WTILE_F * 4)  // 20736 B

__global__ void __launch_bounds__(CW * 32)
k_conf(const float4* __restrict__ scores4,
       const float4* __restrict__ locs) {
    extern __shared__ float sm[];
    const int wid  = threadIdx.x >> 5;
    const int lane = threadIdx.x & 31;
    const int sub  = lane & 3;
    const int r    = lane >> 2;
    float* buf = sm + wid * WTILE_F;

    const int gw = blockIdx.x * CW + wid;
    const int nw = WGRID * CW;

    float4 v0, v1, v2, v3, v4, v5;
    v5 = make_float4(0.f, 0.f, 0.f, 0.f);
    int t = gw;
    if (t < WNT) {
        const float4* src = scores4 + (size_t)t * WTILE_V4;
        v0 = __ldcs(&src[lane]);
        v1 = __ldcs(&src[lane + 32]);
        v2 = __ldcs(&src[lane + 64]);
        v3 = __ldcs(&src[lane + 96]);
        v4 = __ldcs(&src[lane + 128]);
        if (lane < 2) v5 = __ldcs(&src[lane + 160]);
    }

    for (; t < WNT; t += nw) {
        float4* dst = (float4*)buf;
        dst[lane]       = v0;
        dst[lane + 32]  = v1;
        dst[lane + 64]  = v2;
        dst[lane + 96]  = v3;
        dst[lane + 128] = v4;
        if (lane < 2) dst[lane + 160] = v5;
        __syncwarp();

        int tn = t + nw;
        if (tn < WNT) {
            const float4* src = scores4 + (size_t)tn * WTILE_V4;
            v0 = __ldcs(&src[lane]);
            v1 = __ldcs(&src[lane + 32]);
            v2 = __ldcs(&src[lane + 64]);
            v3 = __ldcs(&src[lane + 96]);
            v4 = __ldcs(&src[lane + 128]);
            if (lane < 2) v5 = __ldcs(&src[lane + 160]);
        }

        const int row = t * WROWS + r;
        int tc = (int)g_tc[row];

        const float* rp = buf + r * C;
        float s0, s1, s2, s3;
        s0 = ex2f(rp[sub]      * L2E);
        s1 = ex2f(rp[sub + 4]  * L2E);
        s2 = ex2f(rp[sub + 8]  * L2E);
        s3 = ex2f(rp[sub + 12] * L2E);
        s0 += ex2f(rp[sub + 16] * L2E);
        s1 += ex2f(rp[sub + 20] * L2E);
        s2 += ex2f(rp[sub + 24] * L2E);
        s3 += ex2f(rp[sub + 28] * L2E);
        s0 += ex2f(rp[sub + 32] * L2E);
        s1 += ex2f(rp[sub + 36] * L2E);
        s2 += ex2f(rp[sub + 40] * L2E);
        s3 += ex2f(rp[sub + 44] * L2E);
        s0 += ex2f(rp[sub + 48] * L2E);
        s1 += ex2f(rp[sub + 52] * L2E);
        s2 += ex2f(rp[sub + 56] * L2E);
        s3 += ex2f(rp[sub + 60] * L2E);
        s0 += ex2f(rp[sub + 64] * L2E);
        s1 += ex2f(rp[sub + 68] * L2E);
        s2 += ex2f(rp[sub + 72] * L2E);
        s3 += ex2f(rp[sub + 76] * L2E);
        float s = (s0 + s1) + (s2 + s3);
        if (sub == 0) s += ex2f(rp[80] * L2E);
        s += __shfl_xor_sync(0xffffffffu, s, 1);
        s += __shfl_xor_sync(0xffffffffu, s, 2);

        if (sub == 0) {
            const int b = row / P;
            float conf = lg2f(s) * LN2 - rp[tc];
            bool pos = tc > 0;
            g_conf_neg[row] = pos ? 0.0f : conf;
            if (pos) {
                atomicAdd(&g_conf_pos[b], (double)conf);
                atomicAdd(&g_n_pos[b], 1);
                float4 bx = locs[row];
                float iw = fmaxf(bx.z - bx.x, 0.0f);
                float ih = fmaxf(bx.w - bx.y, 0.0f);
                float inter = iw * ih;
                float area = (bx.z - bx.x) * (bx.w - bx.y);
                float iou = __fdividef(inter, area + area - inter + EPSF);
                float dious = fminf(fmaxf(iou, -1.0f), 1.0f);
                atomicAdd(&g_loc_pb[b], (double)(1.0f - dious));
            }
        }
        __syncwarp();
    }
}

// ---------------- K-topk: inline override patch + top-k sum (3-pass radix) + fused final ----------------
#define TKT 1024
__global__ void __launch_bounds__(TKT)
k_topk(const float* __restrict__ scores,
       const float4* __restrict__ locs,
       const int*    __restrict__ labels,
       float* __restrict__ out) {
    const int b    = blockIdx.x;
    const int tid  = threadIdx.x;
    const int lane = tid & 31;
    const int wid  = tid >> 5;

    __shared__ unsigned int sv[P];
    __shared__ int hist[2048];
    __shared__ int wtot[32], wsuf[33];
    __shared__ int s_bin, s_kk;
    __shared__ int s_last;

    {
        const uint4* src = (const uint4*)(g_conf_neg + b * P);
        uint4* dst = (uint4*)sv;
        for (int i = tid; i < P / 4; i += TKT) dst[i] = src[i];
    }
    __syncthreads();

    // ---- inline patch of overridden rows (was k_fix): first 64 threads, groups of 4 ----
    if (tid < 64) {
        const int m   = tid >> 2;
        const int sub = tid & 3;
        const unsigned int gmask = 0xFu << ((tid & 31) & ~3);
        unsigned int e = g_force[b * M + m];
        float s = 0.0f;
        int p = 0, j = 0, row = 0;
        const float* rp = scores;
        if (e) {
            p   = (int)(e >> 8);
            j   = (int)(e & 0xffu) - 1;
            row = b * P + p;
            rp  = scores + (size_t)row * C;
            float s0, s1, s2, s3;
            s0 = ex2f(__ldg(&rp[sub])      * L2E);
            s1 = ex2f(__ldg(&rp[sub + 4])  * L2E);
            s2 = ex2f(__ldg(&rp[sub + 8])  * L2E);
            s3 = ex2f(__ldg(&rp[sub + 12]) * L2E);
            s0 += ex2f(__ldg(&rp[sub + 16]) * L2E);
            s1 += ex2f(__ldg(&rp[sub + 20]) * L2E);
            s2 += ex2f(__ldg(&rp[sub + 24]) * L2E);
            s3 += ex2f(__ldg(&rp[sub + 28]) * L2E);
            s0 += ex2f(__ldg(&rp[sub + 32]) * L2E);
            s1 += ex2f(__ldg(&rp[sub + 36]) * L2E);
            s2 += ex2f(__ldg(&rp[sub + 40]) * L2E);
            s3 += ex2f(__ldg(&rp[sub + 44]) * L2E);
            s0 += ex2f(__ldg(&rp[sub + 48]) * L2E);
            s1 += ex2f(__ldg(&rp[sub + 52]) * L2E);
            s2 += ex2f(__ldg(&rp[sub + 56]) * L2E);
            s3 += ex2f(__ldg(&rp[sub + 60]) * L2E);
            s0 += ex2f(__ldg(&rp[sub + 64]) * L2E);
            s1 += ex2f(__ldg(&rp[sub + 68]) * L2E);
            s2 += ex2f(__ldg(&rp[sub + 72]) * L2E);
            s3 += ex2f(__ldg(&rp[sub + 76]) * L2E);
            s = (s0 + s1) + (s2 + s3);
            if (sub == 0) s += ex2f(__ldg(&rp[80]) * L2E);
        }
        s += __shfl_xor_sync(gmask, s, 1);
        s += __shfl_xor_sync(gmask, s, 2);

        if (e && sub == 0) {
            int old_tc = (int)g_tc[row];
            int new_tc = __ldg(&labels[b * M + j]);    // faithful j_idx: filtered index
            float lse = lg2f(s) * LN2;
            float conf_old = lse - __ldg(&rp[old_tc]); // exactly what k_conf computed
            float conf_new = lse - __ldg(&rp[new_tc]);
            if (old_tc > 0) {
                atomicAdd(&g_conf_pos[b], (double)conf_new - (double)conf_old);
            } else {
                sv[p] = 0u;                            // patch in smem (sv already loaded)
                atomicAdd(&g_conf_pos[b], (double)conf_new);
                atomicAdd(&g_n_pos[b], 1);
                float4 bx = __ldg(&locs[row]);
                float iw = fmaxf(bx.z - bx.x, 0.0f);
                float ih = fmaxf(bx.w - bx.y, 0.0f);
                float inter = iw * ih;
                float area = (bx.z - bx.x) * (bx.w - bx.y);
                float iou = __fdividef(inter, area + area - inter + EPSF);
                float dious = fminf(fmaxf(iou, -1.0f), 1.0f);
                atomicAdd(&g_loc_pb[b], (double)(1.0f - dious));
            }
        }
        __threadfence_block();
    }
    __syncthreads();

    long long k = 3LL * (long long)g_n_pos[b];
    double result = 0.0;

    if (k >= P) {
        double sum = 0.0;
        for (int p = tid; p < P; p += TKT) sum += (double)__uint_as_float(sv[p]);
        result = blockReduceSumD(sum);
    } else if (k > 0) {
        unsigned int prefix = 0;
        int kk = (int)k;
        #pragma unroll
        for (int pass = 0; pass < 3; pass++) {
            const int sh   = (pass == 0) ? 21 : (pass == 1) ? 10 : 0;
            const int bits = (pass == 2) ? 10 : 11;
            const unsigned int dmask = (1u << bits) - 1u;
            hist[tid] = 0; hist[tid + 1024] = 0;
            __syncthreads();
            for (int base = 0; base < P; base += TKT) {
                int p = base + tid;
                bool in = p < P;
                unsigned int v = in ? sv[p] : 0u;
                bool match = in && (pass == 0 || (v >> (sh + bits)) == prefix);
                unsigned int act = __ballot_sync(0xffffffffu, match);
                if (match) {
                    unsigned int bin = (v >> sh) & dmask;
                    unsigned int peers = __match_any_sync(act, bin);
                    if ((__ffs(peers) - 1) == lane)
                        atomicAdd(&hist[bin], (int)__popc(peers));
                }
            }
            __syncthreads();
            int h_lo = hist[2 * tid], h_hi = hist[2 * tid + 1];
            int tot = h_lo + h_hi;
            int v = tot;
            #pragma unroll
            for (int o = 1; o < 32; o <<= 1) {
                int u = __shfl_down_sync(0xffffffffu, v, o);
                if (lane + o < 32) v += u;
            }
            if (lane == 0) wtot[wid] = v;
            __syncthreads();
            if (wid == 0) {
                int x = wtot[lane];
                #pragma unroll
                for (int o = 1; o < 32; o <<= 1) {
                    int u = __shfl_down_sync(0xffffffffu, x, o);
                    if (lane + o < 32) x += u;
                }
                wsuf[lane] = x;
                if (lane == 0) wsuf[32] = 0;
            }
            __syncthreads();
            int after = (v - tot) + wsuf[wid + 1];
            int cge0 = tot + after;
            int cge1 = h_hi + after;
            int cge2 = after;
            if (cge0 >= kk && cge1 < kk) { s_bin = 2 * tid;     s_kk = kk - cge1; }
            if (cge1 >= kk && cge2 < kk) { s_bin = 2 * tid + 1; s_kk = kk - cge2; }
            __syncthreads();
            prefix = (prefix << bits) | (unsigned int)s_bin;
            kk = s_kk;
            __syncthreads();
        }
        unsigned int thr = prefix;
        double sum = 0.0;
        for (int p = tid; p < P; p += TKT) {
            unsigned int v = sv[p];
            if (v > thr) sum += (double)__uint_as_float(v);
        }
        result = blockReduceSumD(sum);
        if (tid == 0) result += (double)kk * (double)__uint_as_float(thr);
    }
    if (tid == 0) g_hard_pb[b] = result;

    __threadfence();
    if (tid == 0) {
        unsigned int t = atomicAdd(&g_done, 1u);
        s_last = (t == B - 1u) ? 1 : 0;
    }
    __syncthreads();
    if (s_last) {
        double cp = 0.0, hs = 0.0, ls = 0.0;
        long long np = 0;
        if (tid < B) {
            cp = g_conf_pos[tid];
            hs = g_hard_pb[tid];
            ls = g_loc_pb[tid];
            np = g_n_pos[tid];
        }
        double cps = blockReduceSumD(cp);
        double hss = blockReduceSumD(hs);
        double lss = blockReduceSumD(ls);
        double nps = blockReduceSumD((double)np);
        if (tid == 0) {
            float conf_loss = (float)((hss + cps) / nps);
            float loc_loss  = (float)(lss / fmax(nps, 1.0));
            out[0] = conf_loss + loc_loss;  // ALPHA = 1.0
        }
    }
}

// ---------------- launch: fork k_obj onto side stream, join before k_topk ----------------
extern "C" void kernel_launch(void* const* d_in, const int* in_sizes, int n_in,
                              void* d_out, int out_size) {
    const float* locs   = (const float*)d_in[0];  // [B,P,4]
    const float* scores = (const float*)d_in[1];  // [B,P,C]
    const float* boxes  = (const float*)d_in[2];  // [B,M,4]
    const int*   labels = (const int*)  d_in[3];  // [B,M]
    const float* priors = (const float*)d_in[4];  // [P,4]
    float* out = (float*)d_out;

    static bool init_done = false;
    static cudaStream_t s2 = nullptr;
    static cudaEvent_t ev_fork = nullptr, ev_join = nullptr;
    if (!init_done) {
        init_done = true;
        if (cudaStreamCreateWithFlags(&s2, cudaStreamNonBlocking) != cudaSuccess) s2 = nullptr;
        if (s2) {
            if (cudaEventCreateWithFlags(&ev_fork, cudaEventDisableTiming) != cudaSuccess ||
                cudaEventCreateWithFlags(&ev_join, cudaEventDisableTiming) != cudaSuccess) {
                s2 = nullptr;
            }
        }
        cudaFuncSetAttribute(k_conf, cudaFuncAttributeMaxDynamicSharedMemorySize, WSMEM);
    }

    if (s2) {
        cudaEventRecord(ev_fork, 0);
        cudaStreamWaitEvent(s2, ev_fork, 0);
        k_obj<<<OBJ_GRID, OBJ_TPB, 0, s2>>>((const float4*)boxes, (const float4*)priors);
        cudaEventRecord(ev_join, s2);

        k_match<<<MGRID, MT>>>((const float4*)boxes, labels, (const float4*)priors);
        k_conf<<<WGRID, CW * 32, WSMEM>>>((const float4*)scores, (const float4*)locs);

        cudaStreamWaitEvent(0, ev_join, 0);
    } else {
        k_obj<<<OBJ_GRID, OBJ_TPB>>>((const float4*)boxes, (const float4*)priors);
        k_match<<<MGRID, MT>>>((const float4*)boxes, labels, (const float4*)priors);
        k_conf<<<WGRID, CW * 32, WSMEM>>>((const float4*)scores, (const float4*)locs);
    }

    k_topk<<<B, TKT>>>(scores, (const float4*)locs, labels, out);
}